// round 3
// baseline (speedup 1.0000x reference)
#include <cuda_runtime.h>

#define NB 2
#define NEG 0.2f

// ---------------- scratch (__device__ globals; no allocation) ----------------
__device__ float g_t1 [NB*64*64*64*64];   // stage1 mid   [2,64,64^3]
__device__ float g_x1 [NB*64*64*64*64];   // stage1 out
__device__ float g_xd1[NB*128*32*32*32];  // down1 out
__device__ float g_t2 [NB*128*32*32*32];
__device__ float g_x2 [NB*128*32*32*32];
__device__ float g_xd2[NB*256*16*16*16];
__device__ float g_t3 [NB*256*16*16*16];
__device__ float g_x3 [NB*256*16*16*16];
__device__ float g_x4 [NB*128*8*8*8];
__device__ float g_m2 [NB*32*32*32];
__device__ float g_m3 [NB*16*16*16];
__device__ int   g_list1[NB*64*64*64];
__device__ int   g_list2[NB*32*32*32];
__device__ int   g_list3[NB*16*16*16];
__device__ int   g_cnt[3];
// repacked weights: [tap][cin][cout], cout contiguous (coalesced)
__device__ float g_w1a[27*3*64];
__device__ float g_w1b[27*64*64];
__device__ float g_w1d[3*64];
__device__ float g_wd1[27*64*128];
__device__ float g_w2a[27*128*128];
__device__ float g_w2b[27*128*128];
__device__ float g_wd2[27*128*256];
__device__ float g_w3a[27*256*256];
__device__ float g_w3b[27*256*256];
__device__ float g_wd3[27*256*128];

__device__ __forceinline__ float lrelu(float v){ return v >= 0.f ? v : NEG*v; }

// ---------------- helper kernels ----------------
__global__ void reset_k(){ if (threadIdx.x < 3) g_cnt[threadIdx.x] = 0; }

__global__ void lrelu_copy_k(const float* __restrict__ in, float* __restrict__ out, int n){
    int i  = blockIdx.x*blockDim.x + threadIdx.x;
    int st = gridDim.x*blockDim.x;
    for (int j = i; j < n; j += st){ float v = in[j]; out[j] = lrelu(v); }
}

// w layout [COUT][CIN][K3] -> wr[(k*CIN+ic)*COUT + oc]
__global__ void repack_k(const float* __restrict__ w, float* __restrict__ wr,
                         int CIN, int COUT, int K3){
    int i = blockIdx.x*blockDim.x + threadIdx.x;
    int tot = COUT*CIN*K3;
    if (i >= tot) return;
    int oc = i / (CIN*K3);
    int r  = i % (CIN*K3);
    int ic = r / K3;
    int k  = r % K3;
    wr[(k*CIN + ic)*COUT + oc] = w[i];
}

// maxpool 3x3x3 stride 2 pad 1 of the mask
__global__ void down_mask_k(const float* __restrict__ in, float* __restrict__ out,
                            int Din, int Dout){
    int i = blockIdx.x*blockDim.x + threadIdx.x;
    int tot = NB*Dout*Dout*Dout;
    if (i >= tot) return;
    int ox = i % Dout, t = i / Dout;
    int oy = t % Dout; t /= Dout;
    int oz = t % Dout; int b = t / Dout;
    float m = 0.f;
    for (int kz = 0; kz < 3; kz++){
        int iz = 2*oz - 1 + kz; if ((unsigned)iz >= (unsigned)Din) continue;
        for (int ky = 0; ky < 3; ky++){
            int iy = 2*oy - 1 + ky; if ((unsigned)iy >= (unsigned)Din) continue;
            for (int kx = 0; kx < 3; kx++){
                int ix = 2*ox - 1 + kx; if ((unsigned)ix >= (unsigned)Din) continue;
                m = fmaxf(m, in[((b*Din + iz)*Din + iy)*Din + ix]);
            }
        }
    }
    out[i] = m;
}

__global__ void build_list_k(const float* __restrict__ m, int tot,
                             int* __restrict__ list, int* __restrict__ cnt){
    int i = blockIdx.x*blockDim.x + threadIdx.x;
    if (i < tot && m[i] != 0.f){
        int p = atomicAdd(cnt, 1);
        list[p] = i;
    }
}

// ---------------- the conv kernel ----------------
// 3x3x3 conv, pad 1, stride 1 or 2.  thread = out channel, block = 32 voxels.
// list != nullptr -> gather active voxels; else dense over all NB*Dout^3 outputs.
// in_mask (nullable) gives per-tap skip AND per-voxel zeroing of inactive
// inputs (so producers need not zero-fill inactive sites of `in`).
// ident  (nullable): add ident[b][oc][voxel]  (residual identity, same res as out)
// identw (nullable): add 1x1x1 conv of identx (3 ch) with identw[3][COUT]
template<int CIN, int COUT, int CINC>
__global__ void __launch_bounds__(COUT) conv3d_k(
    const float* __restrict__ in, const float* __restrict__ wr,
    const float* __restrict__ in_mask,
    const int* __restrict__ list, const int* __restrict__ cnt,
    int Din, int Dout, int stride,
    const float* __restrict__ ident,
    const float* __restrict__ identx, const float* __restrict__ identw,
    int do_leaky,
    float* __restrict__ out)
{
    constexpr int VB = 32;
    __shared__ int   s_soff [VB];
    __shared__ int   s_obase[VB];
    __shared__ int   s_xbase[VB];
    __shared__ __align__(16) float s_in[CINC*VB];
    __shared__ float s_w[CINC*COUT];

    const int tid   = threadIdx.x;
    const int Din3  = Din*Din*Din;
    const int Dout3 = Dout*Dout*Dout;
    const int n     = list ? *cnt : NB*Dout3;
    const int vbase = blockIdx.x * VB;

    int vb = 0, vz = 0, vy = 0, vx = 0;
    int vvalid = 0;
    if (tid < VB){
        int vi = vbase + tid;
        int ob = -1, xb = -1;
        if (vi < n){
            int id = list ? list[vi] : vi;
            vx = id % Dout; id /= Dout;
            vy = id % Dout; id /= Dout;
            vz = id % Dout; vb = id / Dout;
            int sp = (vz*Dout + vy)*Dout + vx;
            ob = vb*COUT*Dout3 + sp;
            xb = vb*3*Dout3 + sp;
            vvalid = 1;
        }
        s_obase[tid] = ob;
        s_xbase[tid] = xb;
    }
    if (!__syncthreads_or(vvalid)) return;

    float acc[VB];
    #pragma unroll
    for (int v = 0; v < VB; v++) acc[v] = 0.f;

    for (int t = 0; t < 27; t++){
        const int kz = t/9, ky = (t/3)%3, kx = t%3;
        int pred = 0;
        if (tid < VB){
            int off = -1;
            if (vvalid){
                int iz = vz*stride - 1 + kz;
                int iy = vy*stride - 1 + ky;
                int ix = vx*stride - 1 + kx;
                if ((unsigned)iz < (unsigned)Din && (unsigned)iy < (unsigned)Din &&
                    (unsigned)ix < (unsigned)Din){
                    int sp = (iz*Din + iy)*Din + ix;
                    if (!in_mask || in_mask[vb*Din3 + sp] != 0.f)
                        off = vb*CIN*Din3 + sp;
                }
            }
            s_soff[tid] = off;
            pred = (off >= 0);
        }
        if (!__syncthreads_or(pred)) continue;   // tap fully inactive -> skip

        for (int cc = 0; cc < CIN; cc += CINC){
            #pragma unroll 1
            for (int i = tid; i < CINC*COUT; i += COUT)
                s_w[i] = wr[(t*CIN + cc)*COUT + i];
            #pragma unroll 1
            for (int i = tid; i < CINC*VB; i += COUT){
                int ic = i / VB, v = i % VB;
                int off = s_soff[v];
                s_in[i] = (off >= 0) ? in[off + (cc + ic)*Din3] : 0.f;
            }
            __syncthreads();
            #pragma unroll
            for (int ic = 0; ic < CINC; ic++){
                float wv = s_w[ic*COUT + tid];
                const float4* s4 = reinterpret_cast<const float4*>(s_in + ic*VB);
                #pragma unroll
                for (int q = 0; q < VB/4; q++){
                    float4 a = s4[q];
                    acc[4*q+0] = fmaf(wv, a.x, acc[4*q+0]);
                    acc[4*q+1] = fmaf(wv, a.y, acc[4*q+1]);
                    acc[4*q+2] = fmaf(wv, a.z, acc[4*q+2]);
                    acc[4*q+3] = fmaf(wv, a.w, acc[4*q+3]);
                }
            }
            __syncthreads();
        }
    }

    #pragma unroll 1
    for (int v = 0; v < VB; v++){
        int ob = s_obase[v];
        if (ob < 0) continue;
        float val = acc[v];
        if (ident)  val += ident[ob + tid*Dout3];
        if (identw){
            int xb = s_xbase[v];
            val = fmaf(identw[tid],          identx[xb],           val);
            val = fmaf(identw[COUT + tid],   identx[xb + Dout3],   val);
            val = fmaf(identw[2*COUT + tid], identx[xb + 2*Dout3], val);
        }
        if (do_leaky) val = lrelu(val);
        out[ob + tid*Dout3] = val;
    }
}

// ---------------- final pooled reduce ----------------
__global__ void reduce_k(const float* __restrict__ x4, float* __restrict__ out){
    int b  = blockIdx.x >> 7;
    int oc = blockIdx.x & 127;
    const float* p = x4 + (b*128 + oc)*512;
    int tid = threadIdx.x;   // 128 threads
    float s = 0.f, mx = -3.402823466e38f;
    for (int i = tid; i < 512; i += 128){ float v = p[i]; s += v; mx = fmaxf(mx, v); }
    __shared__ float ss[128], sm[128];
    ss[tid] = s; sm[tid] = mx;
    __syncthreads();
    for (int o = 64; o > 0; o >>= 1){
        if (tid < o){ ss[tid] += ss[tid + o]; sm[tid] = fmaxf(sm[tid], sm[tid + o]); }
        __syncthreads();
    }
    if (tid == 0){
        out[b*256 + oc]       = ss[0] * (1.f/512.f);
        out[b*256 + 128 + oc] = sm[0];
    }
}

// ---------------- launch ----------------
extern "C" void kernel_launch(void* const* d_in, const int* in_sizes, int n_in,
                              void* d_out, int out_size){
    const float* x    = (const float*)d_in[0];
    const float* mask = (const float*)d_in[1];
    const float* w1a  = (const float*)d_in[2];
    const float* w1b  = (const float*)d_in[3];
    const float* w1d  = (const float*)d_in[4];
    const float* wd1  = (const float*)d_in[5];
    const float* w2a  = (const float*)d_in[6];
    const float* w2b  = (const float*)d_in[7];
    const float* wd2  = (const float*)d_in[8];
    const float* w3a  = (const float*)d_in[9];
    const float* w3b  = (const float*)d_in[10];
    const float* wd3  = (const float*)d_in[11];
    float* out = (float*)d_out;

    float *t1,*x1,*xd1,*t2,*x2,*xd2,*t3,*x3,*x4,*m2,*m3;
    int *l1,*l2,*l3,*cnt;
    float *w1ar,*w1br,*w1dr,*wd1r,*w2ar,*w2br,*wd2r,*w3ar,*w3br,*wd3r;
    cudaGetSymbolAddress((void**)&t1 , g_t1 );
    cudaGetSymbolAddress((void**)&x1 , g_x1 );
    cudaGetSymbolAddress((void**)&xd1, g_xd1);
    cudaGetSymbolAddress((void**)&t2 , g_t2 );
    cudaGetSymbolAddress((void**)&x2 , g_x2 );
    cudaGetSymbolAddress((void**)&xd2, g_xd2);
    cudaGetSymbolAddress((void**)&t3 , g_t3 );
    cudaGetSymbolAddress((void**)&x3 , g_x3 );
    cudaGetSymbolAddress((void**)&x4 , g_x4 );
    cudaGetSymbolAddress((void**)&m2 , g_m2 );
    cudaGetSymbolAddress((void**)&m3 , g_m3 );
    cudaGetSymbolAddress((void**)&l1 , g_list1);
    cudaGetSymbolAddress((void**)&l2 , g_list2);
    cudaGetSymbolAddress((void**)&l3 , g_list3);
    cudaGetSymbolAddress((void**)&cnt, g_cnt);
    cudaGetSymbolAddress((void**)&w1ar, g_w1a);
    cudaGetSymbolAddress((void**)&w1br, g_w1b);
    cudaGetSymbolAddress((void**)&w1dr, g_w1d);
    cudaGetSymbolAddress((void**)&wd1r, g_wd1);
    cudaGetSymbolAddress((void**)&w2ar, g_w2a);
    cudaGetSymbolAddress((void**)&w2br, g_w2b);
    cudaGetSymbolAddress((void**)&wd2r, g_wd2);
    cudaGetSymbolAddress((void**)&w3ar, g_w3a);
    cudaGetSymbolAddress((void**)&w3br, g_w3b);
    cudaGetSymbolAddress((void**)&wd3r, g_wd3);

    reset_k<<<1,32>>>();

    repack_k<<<(64*3*27   +255)/256,256>>>(w1a, w1ar, 3,   64,  27);
    repack_k<<<1,256>>>(w1d, w1dr, 3, 64, 1);
    repack_k<<<(64*64*27  +255)/256,256>>>(w1b, w1br, 64,  64,  27);
    repack_k<<<(128*64*27 +255)/256,256>>>(wd1, wd1r, 64,  128, 27);
    repack_k<<<(128*128*27+255)/256,256>>>(w2a, w2ar, 128, 128, 27);
    repack_k<<<(128*128*27+255)/256,256>>>(w2b, w2br, 128, 128, 27);
    repack_k<<<(256*128*27+255)/256,256>>>(wd2, wd2r, 128, 256, 27);
    repack_k<<<(256*256*27+255)/256,256>>>(w3a, w3ar, 256, 256, 27);
    repack_k<<<(256*256*27+255)/256,256>>>(w3b, w3br, 256, 256, 27);
    repack_k<<<(128*256*27+255)/256,256>>>(wd3, wd3r, 256, 128, 27);

    down_mask_k<<<(NB*32768+255)/256,256>>>(mask, m2, 64, 32);
    down_mask_k<<<(NB*4096 +255)/256,256>>>(m2,   m3, 32, 16);

    build_list_k<<<(NB*262144+255)/256,256>>>(mask, NB*262144, l1, cnt+0);
    build_list_k<<<(NB*32768 +255)/256,256>>>(m2,   NB*32768,  l2, cnt+1);
    build_list_k<<<(NB*4096  +255)/256,256>>>(m3,   NB*4096,   l3, cnt+2);

    // NOTE: no zero-fill of t1/x1/t2/t3 — every consumer reads them only at
    // mask-active sites (enforced by in_mask in conv3d_k), and producers write
    // all such sites.

    // stage 1 (sparse, ~5% active)
    conv3d_k<3,64,3>  <<<16384,64>>>(x,  w1ar, mask, l1, cnt+0, 64,64,1,
                                     nullptr, nullptr, nullptr, 1, t1);
    conv3d_k<64,64,32><<<16384,64>>>(t1, w1br, mask, l1, cnt+0, 64,64,1,
                                     nullptr, x, w1dr, 1, x1);
    // down1 (dense out, sparse in -> tap skip via m1)
    conv3d_k<64,128,32><<<2048,128>>>(x1, wd1r, mask, nullptr, nullptr, 64,32,2,
                                      nullptr, nullptr, nullptr, 1, xd1);
    // stage 2 (m2 ~75% active)
    conv3d_k<128,128,32><<<2048,128>>>(xd1, w2ar, nullptr, l2, cnt+1, 32,32,1,
                                       nullptr, nullptr, nullptr, 1, t2);
    lrelu_copy_k<<<4096,256>>>(xd1, x2, NB*128*32768);
    conv3d_k<128,128,32><<<2048,128>>>(t2, w2br, m2, l2, cnt+1, 32,32,1,
                                       xd1, nullptr, nullptr, 1, x2);
    // down2
    conv3d_k<128,256,32><<<256,256>>>(x2, wd2r, nullptr, nullptr, nullptr, 32,16,2,
                                      nullptr, nullptr, nullptr, 1, xd2);
    // stage 3 (m3 ~100% active)
    conv3d_k<256,256,32><<<256,256>>>(xd2, w3ar, nullptr, l3, cnt+2, 16,16,1,
                                      nullptr, nullptr, nullptr, 1, t3);
    lrelu_copy_k<<<1024,256>>>(xd2, x3, NB*256*4096);
    conv3d_k<256,256,32><<<256,256>>>(t3, w3br, m3, l3, cnt+2, 16,16,1,
                                      xd2, nullptr, nullptr, 1, x3);
    // down3
    conv3d_k<256,128,32><<<32,128>>>(x3, wd3r, nullptr, nullptr, nullptr, 16,8,2,
                                     nullptr, nullptr, nullptr, 1, x4);
    // pooled head
    reduce_k<<<256,128>>>(x4, out);
}

// round 4
// speedup vs baseline: 2.3148x; 2.3148x over previous
#include <cuda_runtime.h>

#define NB 2
#define NEG 0.2f

// ---------------- scratch (__device__ globals; no allocation) ----------------
// All intermediates are CHANNEL-LAST: [b][spatial][C]
__device__ float g_t1 [NB*64*64*64*64];
__device__ float g_x1 [NB*64*64*64*64];
__device__ float g_xd1[NB*32*32*32*128];
__device__ float g_t2 [NB*32*32*32*128];
__device__ float g_x2 [NB*32*32*32*128];
__device__ float g_xd2[NB*16*16*16*256];
__device__ float g_t3 [NB*16*16*16*256];
__device__ float g_x3 [NB*16*16*16*256];
__device__ float g_x4 [NB*8*8*8*128];
__device__ float g_m2 [NB*32*32*32];
__device__ float g_m3 [NB*16*16*16];
__device__ int   g_list1[NB*64*64*64];
__device__ int   g_list2[NB*32*32*32];
__device__ int   g_list3[NB*16*16*16];
__device__ int   g_cnt[3];
// repacked weights: [tap][cin][cout], cout contiguous
__device__ float g_w1a[27*3*64];
__device__ float g_w1b[27*64*64];
__device__ float g_w1d[3*64];
__device__ float g_wd1[27*64*128];
__device__ float g_w2a[27*128*128];
__device__ float g_w2b[27*128*128];
__device__ float g_wd2[27*128*256];
__device__ float g_w3a[27*256*256];
__device__ float g_w3b[27*256*256];
__device__ float g_wd3[27*256*128];

__device__ __forceinline__ float lrelu(float v){ return v >= 0.f ? v : NEG*v; }

// ---------------- helper kernels ----------------
__global__ void reset_k(){ if (threadIdx.x < 3) g_cnt[threadIdx.x] = 0; }

// out[i] = (m==null || m[i/C]!=0) ? lrelu(in[i]) : 0
__global__ void fill_k(const float* __restrict__ in, const float* __restrict__ m,
                       float* __restrict__ out, int C, int n){
    int i  = blockIdx.x*blockDim.x + threadIdx.x;
    int st = gridDim.x*blockDim.x;
    for (int j = i; j < n; j += st){
        float v = in[j];
        float r = lrelu(v);
        if (m && m[j/C] == 0.f) r = 0.f;
        out[j] = r;
    }
}

// w layout [COUT][CIN][K3] -> wr[(k*CIN+ic)*COUT + oc]
__global__ void repack_k(const float* __restrict__ w, float* __restrict__ wr,
                         int CIN, int COUT, int K3){
    int i = blockIdx.x*blockDim.x + threadIdx.x;
    int tot = COUT*CIN*K3;
    if (i >= tot) return;
    int oc = i / (CIN*K3);
    int r  = i % (CIN*K3);
    int ic = r / K3;
    int k  = r % K3;
    wr[(k*CIN + ic)*COUT + oc] = w[i];
}

// maxpool 3x3x3 stride 2 pad 1 of the mask
__global__ void down_mask_k(const float* __restrict__ in, float* __restrict__ out,
                            int Din, int Dout){
    int i = blockIdx.x*blockDim.x + threadIdx.x;
    int tot = NB*Dout*Dout*Dout;
    if (i >= tot) return;
    int ox = i % Dout, t = i / Dout;
    int oy = t % Dout; t /= Dout;
    int oz = t % Dout; int b = t / Dout;
    float m = 0.f;
    for (int kz = 0; kz < 3; kz++){
        int iz = 2*oz - 1 + kz; if ((unsigned)iz >= (unsigned)Din) continue;
        for (int ky = 0; ky < 3; ky++){
            int iy = 2*oy - 1 + ky; if ((unsigned)iy >= (unsigned)Din) continue;
            for (int kx = 0; kx < 3; kx++){
                int ix = 2*ox - 1 + kx; if ((unsigned)ix >= (unsigned)Din) continue;
                m = fmaxf(m, in[((b*Din + iz)*Din + iy)*Din + ix]);
            }
        }
    }
    out[i] = m;
}

__global__ void build_list_k(const float* __restrict__ m, int tot,
                             int* __restrict__ list, int* __restrict__ cnt){
    int i = blockIdx.x*blockDim.x + threadIdx.x;
    if (i < tot && m[i] != 0.f){
        int p = atomicAdd(cnt, 1);
        list[p] = i;
    }
}

// ---------------- conv kernel (channel-last) ----------------
// 3x3x3 conv pad1, stride 1|2. thread = out channel, block = VB voxels.
// in: channel-last [b][sp][CIN] if IN_CHLAST else NCDHW.
// out: channel-last [b][sp][COUT]; leaky applied always.
// list: active output voxel ids (linear over [b][Dout^3]) or nullptr (dense).
// in_mask: per input site; inactive -> contributes zero (and allows tap skip).
// ident: channel-last residual at out resolution. identx/identw: 1x1x1 of
// NCDHW 3-channel identx with identw[3][COUT].
template<int CIN, int COUT, int CINC, int VB, bool IN_CHLAST>
__global__ void __launch_bounds__(COUT) conv_k(
    const float* __restrict__ in, const float* __restrict__ wr,
    const float* __restrict__ in_mask,
    const int* __restrict__ list, const int* __restrict__ cnt,
    int Din, int Dout, int stride,
    const float* __restrict__ ident,
    const float* __restrict__ identx, const float* __restrict__ identw,
    float* __restrict__ out)
{
    __shared__ int s_base[VB];                 // input gather base or -1
    __shared__ int s_out [VB];                 // b*Dout3+sp or -1
    __shared__ __align__(16) float s_in[VB][CINC];

    const int tid   = threadIdx.x;
    const int Din3  = Din*Din*Din;
    const int Dout3 = Dout*Dout*Dout;
    const int n     = list ? *cnt : NB*Dout3;
    const int vbase = blockIdx.x * VB;

    int vb=0,vz=0,vy=0,vx=0,vvalid=0;
    if (tid < VB){
        int vi = vbase + tid;
        int ob = -1;
        if (vi < n){
            int id = list ? list[vi] : vi;
            vx = id % Dout; id /= Dout;
            vy = id % Dout; id /= Dout;
            vz = id % Dout; vb = id / Dout;
            ob = vb*Dout3 + (vz*Dout + vy)*Dout + vx;
            vvalid = 1;
        }
        s_out[tid] = ob;
    }
    if (!__syncthreads_or(vvalid)) return;

    float acc[VB];
    #pragma unroll
    for (int v = 0; v < VB; v++) acc[v] = 0.f;

    for (int t = 0; t < 27; t++){
        const int kz = t/9, ky = (t/3)%3, kx = t%3;
        int pred = 0;
        if (tid < VB){
            int base = -1;
            if (vvalid){
                int iz = vz*stride - 1 + kz;
                int iy = vy*stride - 1 + ky;
                int ix = vx*stride - 1 + kx;
                if ((unsigned)iz < (unsigned)Din && (unsigned)iy < (unsigned)Din &&
                    (unsigned)ix < (unsigned)Din){
                    int sp = (iz*Din + iy)*Din + ix;
                    if (!in_mask || in_mask[vb*Din3 + sp] != 0.f)
                        base = IN_CHLAST ? (vb*Din3 + sp)*CIN : vb*CIN*Din3 + sp;
                }
            }
            s_base[tid] = base;
            pred = (base >= 0);
        }
        if (!__syncthreads_or(pred)) continue;   // tap fully inactive

        #pragma unroll 1
        for (int cc = 0; cc < CIN; cc += CINC){
            // weights -> registers (reused across all VB voxels)
            float wreg[CINC];
            #pragma unroll
            for (int c = 0; c < CINC; c++)
                wreg[c] = wr[(t*CIN + cc + c)*COUT + tid];
            // coalesced gather: consecutive threads = consecutive channels
            #pragma unroll 1
            for (int i = tid; i < CINC*VB; i += COUT){
                int v = i / CINC, c = i % CINC;
                int base = s_base[v];
                float val = 0.f;
                if (base >= 0)
                    val = IN_CHLAST ? in[base + cc + c] : in[base + (cc + c)*Din3];
                s_in[v][c] = val;
            }
            __syncthreads();
            if constexpr (CINC % 4 == 0){
                #pragma unroll
                for (int v = 0; v < VB; v++){
                    const float4* row = reinterpret_cast<const float4*>(s_in[v]);
                    float a = acc[v];
                    #pragma unroll
                    for (int q = 0; q < CINC/4; q++){
                        float4 r = row[q];
                        a = fmaf(wreg[4*q+0], r.x, a);
                        a = fmaf(wreg[4*q+1], r.y, a);
                        a = fmaf(wreg[4*q+2], r.z, a);
                        a = fmaf(wreg[4*q+3], r.w, a);
                    }
                    acc[v] = a;
                }
            } else {
                #pragma unroll
                for (int v = 0; v < VB; v++){
                    float a = acc[v];
                    #pragma unroll
                    for (int c = 0; c < CINC; c++)
                        a = fmaf(wreg[c], s_in[v][c], a);
                    acc[v] = a;
                }
            }
            __syncthreads();
        }
    }

    #pragma unroll
    for (int v = 0; v < VB; v++){
        int ob = s_out[v];
        if (ob < 0) continue;
        float val = acc[v];
        if (ident) val += ident[ob*COUT + tid];
        if (identw){
            int b = ob / Dout3, sp = ob - b*Dout3;
            const float* xp = identx + b*3*Dout3 + sp;
            val = fmaf(identw[tid],          xp[0],       val);
            val = fmaf(identw[COUT + tid],   xp[Dout3],   val);
            val = fmaf(identw[2*COUT + tid], xp[2*Dout3], val);
        }
        out[ob*COUT + tid] = lrelu(val);
    }
}

// ---------------- final pooled reduce (channel-last x4) ----------------
__global__ void reduce_k(const float* __restrict__ x4, float* __restrict__ out){
    int b  = blockIdx.x;          // 2 blocks
    int oc = threadIdx.x;         // 128 threads
    const float* p = x4 + b*512*128 + oc;
    float s = 0.f, mx = -3.402823466e38f;
    #pragma unroll 8
    for (int sp = 0; sp < 512; sp++){
        float v = p[sp*128];
        s += v; mx = fmaxf(mx, v);
    }
    out[b*256 + oc]       = s * (1.f/512.f);
    out[b*256 + 128 + oc] = mx;
}

// ---------------- launch ----------------
extern "C" void kernel_launch(void* const* d_in, const int* in_sizes, int n_in,
                              void* d_out, int out_size){
    const float* x    = (const float*)d_in[0];
    const float* mask = (const float*)d_in[1];
    const float* w1a  = (const float*)d_in[2];
    const float* w1b  = (const float*)d_in[3];
    const float* w1d  = (const float*)d_in[4];
    const float* wd1  = (const float*)d_in[5];
    const float* w2a  = (const float*)d_in[6];
    const float* w2b  = (const float*)d_in[7];
    const float* wd2  = (const float*)d_in[8];
    const float* w3a  = (const float*)d_in[9];
    const float* w3b  = (const float*)d_in[10];
    const float* wd3  = (const float*)d_in[11];
    float* out = (float*)d_out;

    float *t1,*x1,*xd1,*t2,*x2,*xd2,*t3,*x3,*x4,*m2,*m3;
    int *l1,*l2,*l3,*cnt;
    float *w1ar,*w1br,*w1dr,*wd1r,*w2ar,*w2br,*wd2r,*w3ar,*w3br,*wd3r;
    cudaGetSymbolAddress((void**)&t1 , g_t1 );
    cudaGetSymbolAddress((void**)&x1 , g_x1 );
    cudaGetSymbolAddress((void**)&xd1, g_xd1);
    cudaGetSymbolAddress((void**)&t2 , g_t2 );
    cudaGetSymbolAddress((void**)&x2 , g_x2 );
    cudaGetSymbolAddress((void**)&xd2, g_xd2);
    cudaGetSymbolAddress((void**)&t3 , g_t3 );
    cudaGetSymbolAddress((void**)&x3 , g_x3 );
    cudaGetSymbolAddress((void**)&x4 , g_x4 );
    cudaGetSymbolAddress((void**)&m2 , g_m2 );
    cudaGetSymbolAddress((void**)&m3 , g_m3 );
    cudaGetSymbolAddress((void**)&l1 , g_list1);
    cudaGetSymbolAddress((void**)&l2 , g_list2);
    cudaGetSymbolAddress((void**)&l3 , g_list3);
    cudaGetSymbolAddress((void**)&cnt, g_cnt);
    cudaGetSymbolAddress((void**)&w1ar, g_w1a);
    cudaGetSymbolAddress((void**)&w1br, g_w1b);
    cudaGetSymbolAddress((void**)&w1dr, g_w1d);
    cudaGetSymbolAddress((void**)&wd1r, g_wd1);
    cudaGetSymbolAddress((void**)&w2ar, g_w2a);
    cudaGetSymbolAddress((void**)&w2br, g_w2b);
    cudaGetSymbolAddress((void**)&wd2r, g_wd2);
    cudaGetSymbolAddress((void**)&w3ar, g_w3a);
    cudaGetSymbolAddress((void**)&w3br, g_w3b);
    cudaGetSymbolAddress((void**)&wd3r, g_wd3);

    reset_k<<<1,32>>>();

    repack_k<<<(64*3*27   +255)/256,256>>>(w1a, w1ar, 3,   64,  27);
    repack_k<<<1,256>>>(w1d, w1dr, 3, 64, 1);
    repack_k<<<(64*64*27  +255)/256,256>>>(w1b, w1br, 64,  64,  27);
    repack_k<<<(128*64*27 +255)/256,256>>>(wd1, wd1r, 64,  128, 27);
    repack_k<<<(128*128*27+255)/256,256>>>(w2a, w2ar, 128, 128, 27);
    repack_k<<<(128*128*27+255)/256,256>>>(w2b, w2br, 128, 128, 27);
    repack_k<<<(256*128*27+255)/256,256>>>(wd2, wd2r, 128, 256, 27);
    repack_k<<<(256*256*27+255)/256,256>>>(w3a, w3ar, 256, 256, 27);
    repack_k<<<(256*256*27+255)/256,256>>>(w3b, w3br, 256, 256, 27);
    repack_k<<<(128*256*27+255)/256,256>>>(wd3, wd3r, 256, 128, 27);

    down_mask_k<<<(NB*32768+255)/256,256>>>(mask, m2, 64, 32);
    down_mask_k<<<(NB*4096 +255)/256,256>>>(m2,   m3, 32, 16);

    build_list_k<<<(NB*262144+255)/256,256>>>(mask, NB*262144, l1, cnt+0);
    build_list_k<<<(NB*32768 +255)/256,256>>>(m2,   NB*32768,  l2, cnt+1);
    build_list_k<<<(NB*4096  +255)/256,256>>>(m3,   NB*4096,   l3, cnt+2);

    // ---- stage 1 (m1 ~5% active; t1/x1 defined only at active sites) ----
    conv_k<3,64,3,64,false> <<<8192,64>>>(x,  w1ar, mask, l1, cnt+0, 64,64,1,
                                          nullptr, nullptr, nullptr, t1);
    conv_k<64,64,16,64,true><<<8192,64>>>(t1, w1br, mask, l1, cnt+0, 64,64,1,
                                          nullptr, x, w1dr, x1);
    // ---- down1: output nonzero only at m2-active sites -> gather over list2
    conv_k<64,128,16,64,true><<<1024,128>>>(x1, wd1r, mask, l2, cnt+1, 64,32,2,
                                            nullptr, nullptr, nullptr, xd1);
    // ---- stage 2 (m2 ~75%) ----
    conv_k<128,128,16,64,true><<<1024,128>>>(xd1, w2ar, m2, l2, cnt+1, 32,32,1,
                                             nullptr, nullptr, nullptr, t2);
    // x2 = leaky(xd1) at active sites (overwritten below), 0 elsewhere
    fill_k<<<4096,256>>>(xd1, m2, x2, 128, NB*32768*128);
    conv_k<128,128,16,64,true><<<1024,128>>>(t2, w2br, m2, l2, cnt+1, 32,32,1,
                                             xd1, nullptr, nullptr, x2);
    // ---- down2 (dense; x2 fully defined) ----
    conv_k<128,256,16,32,true><<<256,256>>>(x2, wd2r, nullptr, nullptr, nullptr,
                                            32,16,2, nullptr, nullptr, nullptr, xd2);
    // ---- stage 3 (m3 ~100%) ----
    conv_k<256,256,16,32,true><<<256,256>>>(xd2, w3ar, nullptr, l3, cnt+2, 16,16,1,
                                            nullptr, nullptr, nullptr, t3);
    fill_k<<<2048,256>>>(xd2, nullptr, x3, 256, NB*4096*256);
    conv_k<256,256,16,32,true><<<256,256>>>(t3, w3br, m3, l3, cnt+2, 16,16,1,
                                            xd2, nullptr, nullptr, x3);
    // ---- down3 (dense; x3 fully defined) ----
    conv_k<256,128,16,8,true><<<128,128>>>(x3, wd3r, nullptr, nullptr, nullptr,
                                           16,8,2, nullptr, nullptr, nullptr, x4);
    // ---- pooled head ----
    reduce_k<<<2,128>>>(x4, out);
}

// round 5
// speedup vs baseline: 2.4180x; 1.0446x over previous
#include <cuda_runtime.h>

#define NB 2
#define NEG 0.2f

// ---------------- scratch (__device__ globals; no allocation) ----------------
// All intermediates are CHANNEL-LAST: [b][spatial][C]
__device__ float g_t1 [NB*64*64*64*64];
__device__ float g_x1 [NB*64*64*64*64];
__device__ float g_xd1[NB*32*32*32*128];
__device__ float g_t2 [NB*32*32*32*128];
__device__ float g_x2 [NB*32*32*32*128];
__device__ float g_xd2[NB*16*16*16*256];
__device__ float g_t3 [NB*16*16*16*256];
__device__ float g_x3 [NB*16*16*16*256];
__device__ float g_x4 [NB*8*8*8*128];
__device__ float g_m2 [NB*32*32*32];
__device__ float g_m3 [NB*16*16*16];
__device__ int   g_list1[NB*64*64*64];
__device__ int   g_list2[NB*32*32*32];
__device__ int   g_list3[NB*16*16*16];
__device__ int   g_cnt[3];
// repacked weights: [tap][cin][cout], cout contiguous
__device__ float g_w1a[27*3*64];
__device__ float g_w1b[27*64*64];
__device__ float g_w1d[3*64];
__device__ float g_wd1[27*64*128];
__device__ float g_w2a[27*128*128];
__device__ float g_w2b[27*128*128];
__device__ float g_wd2[27*128*256];
__device__ float g_w3a[27*256*256];
__device__ float g_w3b[27*256*256];
__device__ float g_wd3[27*256*128];

__device__ __forceinline__ float lrelu(float v){ return v >= 0.f ? v : NEG*v; }
__device__ __forceinline__ unsigned sm_addr(const void* p){
    return (unsigned)__cvta_generic_to_shared(p);
}

// ---------------- setup kernels (4 launches total) ----------------
struct RepackArgs {
    const float* src[10];
    float*       dst[10];
    int cin[10], cout[10], k3[10], start[10];
    int ntot;
};

// all weight repacks ([COUT][CIN][K3] -> [(k*CIN+ic)*COUT+oc]) + cnt reset
__global__ void repack_all_k(RepackArgs a){
    int idx = blockIdx.x*blockDim.x + threadIdx.x;
    if (idx < 3) g_cnt[idx] = 0;
    if (idx >= a.ntot) return;
    int s = 0;
    #pragma unroll
    for (int k = 1; k < 10; k++) if (idx >= a.start[k]) s = k;
    int i = idx - a.start[s];
    int CIN = a.cin[s], COUT = a.cout[s], K3 = a.k3[s];
    int oc = i / (CIN*K3);
    int r  = i % (CIN*K3);
    int ic = r / K3;
    int k  = r % K3;
    a.dst[s][(k*CIN + ic)*COUT + oc] = a.src[s][i];
}

// maxpool 3x3x3 stride 2 pad 1 of the mask
__global__ void down_mask_k(const float* __restrict__ in, float* __restrict__ out,
                            int Din, int Dout){
    int i = blockIdx.x*blockDim.x + threadIdx.x;
    int tot = NB*Dout*Dout*Dout;
    if (i >= tot) return;
    int ox = i % Dout, t = i / Dout;
    int oy = t % Dout; t /= Dout;
    int oz = t % Dout; int b = t / Dout;
    float m = 0.f;
    for (int kz = 0; kz < 3; kz++){
        int iz = 2*oz - 1 + kz; if ((unsigned)iz >= (unsigned)Din) continue;
        for (int ky = 0; ky < 3; ky++){
            int iy = 2*oy - 1 + ky; if ((unsigned)iy >= (unsigned)Din) continue;
            for (int kx = 0; kx < 3; kx++){
                int ix = 2*ox - 1 + kx; if ((unsigned)ix >= (unsigned)Din) continue;
                m = fmaxf(m, in[((b*Din + iz)*Din + iy)*Din + ix]);
            }
        }
    }
    out[i] = m;
}

// builds l1 (from mask), l2 (from m2), and m3 (down_mask of m2) in one launch
__global__ void fuse_k(const float* __restrict__ mask, const float* __restrict__ m2,
                       float* __restrict__ m3, int* __restrict__ l1,
                       int* __restrict__ l2, int* __restrict__ cnt){
    const int A = NB*262144, B = NB*32768, C = NB*4096;
    int idx = blockIdx.x*blockDim.x + threadIdx.x;
    if (idx < A){
        if (mask[idx] != 0.f){ int p = atomicAdd(cnt+0, 1); l1[p] = idx; }
    } else if (idx < A+B){
        int i = idx - A;
        if (m2[i] != 0.f){ int p = atomicAdd(cnt+1, 1); l2[p] = i; }
    } else if (idx < A+B+C){
        int i = idx - A - B;
        int ox = i % 16, t = i / 16;
        int oy = t % 16; t /= 16;
        int oz = t % 16; int b = t / 16;
        float m = 0.f;
        for (int kz = 0; kz < 3; kz++){
            int iz = 2*oz - 1 + kz; if ((unsigned)iz >= 32u) continue;
            for (int ky = 0; ky < 3; ky++){
                int iy = 2*oy - 1 + ky; if ((unsigned)iy >= 32u) continue;
                for (int kx = 0; kx < 3; kx++){
                    int ix = 2*ox - 1 + kx; if ((unsigned)ix >= 32u) continue;
                    m = fmaxf(m, m2[((b*32 + iz)*32 + iy)*32 + ix]);
                }
            }
        }
        m3[i] = m;
    }
}

__global__ void build_list_k(const float* __restrict__ m, int tot,
                             int* __restrict__ list, int* __restrict__ cnt){
    int i = blockIdx.x*blockDim.x + threadIdx.x;
    if (i < tot && m[i] != 0.f){
        int p = atomicAdd(cnt, 1);
        list[p] = i;
    }
}

// out[i] = (m==null || m[i/C]!=0) ? lrelu(in[i]) : 0
__global__ void fill_k(const float* __restrict__ in, const float* __restrict__ m,
                       float* __restrict__ out, int C, int n){
    int i  = blockIdx.x*blockDim.x + threadIdx.x;
    int st = gridDim.x*blockDim.x;
    for (int j = i; j < n; j += st){
        float v = in[j];
        float r = lrelu(v);
        if (m && m[j/C] == 0.f) r = 0.f;
        out[j] = r;
    }
}

// ---------------- simple conv (only for stage-1a, CIN=3 NCDHW) ----------------
template<int CIN, int COUT, int CINC, int VB>
__global__ void __launch_bounds__(COUT) conv_s_k(
    const float* __restrict__ in, const float* __restrict__ wr,
    const float* __restrict__ in_mask,
    const int* __restrict__ list, const int* __restrict__ cnt,
    int Din, int Dout,
    float* __restrict__ out)
{
    __shared__ int s_base[VB];
    __shared__ int s_out [VB];
    __shared__ float s_in[VB][CINC];

    const int tid   = threadIdx.x;
    const int Din3  = Din*Din*Din;
    const int Dout3 = Dout*Dout*Dout;
    const int n     = *cnt;
    const int vbase = blockIdx.x * VB;

    int vb=0,vz=0,vy=0,vx=0,vvalid=0;
    if (tid < VB){
        int vi = vbase + tid;
        int ob = -1;
        if (vi < n){
            int id = list[vi];
            vx = id % Dout; id /= Dout;
            vy = id % Dout; id /= Dout;
            vz = id % Dout; vb = id / Dout;
            ob = vb*Dout3 + (vz*Dout + vy)*Dout + vx;
            vvalid = 1;
        }
        s_out[tid] = ob;
    }
    if (!__syncthreads_or(vvalid)) return;

    float acc[VB];
    #pragma unroll
    for (int v = 0; v < VB; v++) acc[v] = 0.f;

    for (int t = 0; t < 27; t++){
        int pred = 0;
        if (tid < VB){
            int base = -1;
            if (vvalid){
                int kz = t/9, ky = (t/3)%3, kx = t%3;
                int iz = vz - 1 + kz, iy = vy - 1 + ky, ix = vx - 1 + kx;
                if ((unsigned)iz < (unsigned)Din && (unsigned)iy < (unsigned)Din &&
                    (unsigned)ix < (unsigned)Din){
                    int sp = (iz*Din + iy)*Din + ix;
                    if (in_mask[vb*Din3 + sp] != 0.f)
                        base = vb*CIN*Din3 + sp;   // NCDHW
                }
            }
            s_base[tid] = base;
            pred = (base >= 0);
        }
        if (!__syncthreads_or(pred)) continue;

        float wreg[CINC];
        #pragma unroll
        for (int c = 0; c < CINC; c++)
            wreg[c] = wr[(t*CIN + c)*COUT + tid];
        #pragma unroll 1
        for (int i = tid; i < CINC*VB; i += COUT){
            int v = i / CINC, c = i % CINC;
            int base = s_base[v];
            s_in[v][c] = (base >= 0) ? in[base + c*Din3] : 0.f;
        }
        __syncthreads();
        #pragma unroll
        for (int v = 0; v < VB; v++){
            float a = acc[v];
            #pragma unroll
            for (int c = 0; c < CINC; c++)
                a = fmaf(wreg[c], s_in[v][c], a);
            acc[v] = a;
        }
        __syncthreads();
    }

    #pragma unroll
    for (int v = 0; v < VB; v++){
        int ob = s_out[v];
        if (ob < 0) continue;
        out[ob*COUT + tid] = lrelu(acc[v]);
    }
}

// ---------------- pipelined conv (channel-last in, cp.async double-buffer) ----
// thread = out channel, block = VB voxels. Taps compacted once per block, then
// a flat (tap x cin-chunk) loop with cp.async gather of iteration i+1 while
// computing iteration i.
template<int CIN, int COUT, int CINC, int VB>
__global__ void __launch_bounds__(COUT) convp_k(
    const float* __restrict__ in, const float* __restrict__ wr,
    const float* __restrict__ in_mask,
    const int* __restrict__ list, const int* __restrict__ cnt,
    int Din, int Dout, int stride,
    const float* __restrict__ ident,
    const float* __restrict__ identx, const float* __restrict__ identw,
    float* __restrict__ out)
{
    constexpr int CHUNKS = CIN/CINC;
    constexpr int F4 = VB*CINC/4;                 // float4 elements per iteration
    constexpr int PT = (F4 + COUT - 1)/COUT;      // float4 per thread
    __shared__ int s_tap[27];
    __shared__ int s_ntap;
    __shared__ int s_base[27][VB];
    __shared__ int s_out[VB];
    __shared__ __align__(16) float4 s_in[2][F4];

    const int tid   = threadIdx.x;
    const int Din3  = Din*Din*Din;
    const int Dout3 = Dout*Dout*Dout;
    const int n     = list ? *cnt : NB*Dout3;
    const int vbase = blockIdx.x * VB;

    int vb=0,vz=0,vy=0,vx=0,vvalid=0;
    if (tid < VB){
        int vi = vbase + tid;
        int ob = -1;
        if (vi < n){
            int id = list ? list[vi] : vi;
            vx = id % Dout; id /= Dout;
            vy = id % Dout; id /= Dout;
            vz = id % Dout; vb = id / Dout;
            ob = vb*Dout3 + (vz*Dout + vy)*Dout + vx;
            vvalid = 1;
        }
        s_out[tid] = ob;
    }
    if (!__syncthreads_or(vvalid)) return;
    if (tid == 0) s_ntap = 0;
    __syncthreads();

    // build compacted active-tap table
    for (int t = 0; t < 27; t++){
        int pred = 0;
        if (tid < VB){
            int base = -1;
            if (vvalid){
                int kz = t/9, ky = (t/3)%3, kx = t%3;
                int iz = vz*stride - 1 + kz;
                int iy = vy*stride - 1 + ky;
                int ix = vx*stride - 1 + kx;
                if ((unsigned)iz < (unsigned)Din && (unsigned)iy < (unsigned)Din &&
                    (unsigned)ix < (unsigned)Din){
                    int sp = (iz*Din + iy)*Din + ix;
                    if (!in_mask || in_mask[vb*Din3 + sp] != 0.f)
                        base = (vb*Din3 + sp)*CIN;   // channel-last
                }
            }
            s_base[t][tid] = base;
            pred = (base >= 0);
        }
        if (__syncthreads_or(pred)){
            if (tid == 0) s_tap[s_ntap++] = t;
        }
    }
    __syncthreads();
    const int ntap = s_ntap;
    const int nit  = ntap * CHUNKS;

    float acc[VB];
    #pragma unroll
    for (int v = 0; v < VB; v++) acc[v] = 0.f;

    auto issue = [&](int it, int buf){
        int tap = s_tap[it/CHUNKS];
        int cc  = (it%CHUNKS)*CINC;
        #pragma unroll
        for (int k = 0; k < PT; k++){
            int j = tid + k*COUT;
            if ((F4 % COUT == 0) || (j < F4)){
                int v = j/(CINC/4), c4 = j%(CINC/4);
                int base = s_base[tap][v];
                const float* src = (base >= 0) ? (in + base + cc + c4*4) : in;
                int sz = (base >= 0) ? 16 : 0;
                unsigned dst = sm_addr(&s_in[buf][j]);
                asm volatile("cp.async.ca.shared.global [%0], [%1], 16, %2;\n"
                             :: "r"(dst), "l"(src), "r"(sz));
            }
        }
        asm volatile("cp.async.commit_group;\n");
    };

    issue(0, 0);
    for (int it = 0; it < nit; it++){
        int buf = it & 1;
        int tap = s_tap[it/CHUNKS];
        int cc  = (it%CHUNKS)*CINC;
        float wreg[CINC];
        #pragma unroll
        for (int c = 0; c < CINC; c++)
            wreg[c] = wr[(tap*CIN + cc + c)*COUT + tid];
        if (it + 1 < nit){
            issue(it + 1, buf ^ 1);
            asm volatile("cp.async.wait_group 1;\n");
        } else {
            asm volatile("cp.async.wait_group 0;\n");
        }
        __syncthreads();
        const float4* rows = s_in[buf];
        #pragma unroll
        for (int v = 0; v < VB; v++){
            float a = acc[v];
            #pragma unroll
            for (int q = 0; q < CINC/4; q++){
                float4 r = rows[v*(CINC/4) + q];
                a = fmaf(wreg[4*q+0], r.x, a);
                a = fmaf(wreg[4*q+1], r.y, a);
                a = fmaf(wreg[4*q+2], r.z, a);
                a = fmaf(wreg[4*q+3], r.w, a);
            }
            acc[v] = a;
        }
        __syncthreads();
    }

    #pragma unroll
    for (int v = 0; v < VB; v++){
        int ob = s_out[v];
        if (ob < 0) continue;
        float val = acc[v];
        if (ident) val += ident[ob*COUT + tid];
        if (identw){
            int b = ob / Dout3, sp = ob - b*Dout3;
            const float* xp = identx + b*3*Dout3 + sp;
            val = fmaf(identw[tid],          xp[0],       val);
            val = fmaf(identw[COUT + tid],   xp[Dout3],   val);
            val = fmaf(identw[2*COUT + tid], xp[2*Dout3], val);
        }
        out[ob*COUT + tid] = lrelu(val);
    }
}

// ---------------- final pooled reduce (channel-last x4) ----------------
__global__ void reduce_k(const float* __restrict__ x4, float* __restrict__ out){
    int b  = blockIdx.x;          // 2 blocks
    int oc = threadIdx.x;         // 128 threads
    const float* p = x4 + b*512*128 + oc;
    float s = 0.f, mx = -3.402823466e38f;
    #pragma unroll 8
    for (int sp = 0; sp < 512; sp++){
        float v = p[sp*128];
        s += v; mx = fmaxf(mx, v);
    }
    out[b*256 + oc]       = s * (1.f/512.f);
    out[b*256 + 128 + oc] = mx;
}

// ---------------- launch ----------------
extern "C" void kernel_launch(void* const* d_in, const int* in_sizes, int n_in,
                              void* d_out, int out_size){
    const float* x    = (const float*)d_in[0];
    const float* mask = (const float*)d_in[1];
    const float* w[10] = {
        (const float*)d_in[2],  // w1a
        (const float*)d_in[4],  // w1d (K3=1)
        (const float*)d_in[3],  // w1b
        (const float*)d_in[5],  // wd1
        (const float*)d_in[6],  // w2a
        (const float*)d_in[7],  // w2b
        (const float*)d_in[8],  // wd2
        (const float*)d_in[9],  // w3a
        (const float*)d_in[10], // w3b
        (const float*)d_in[11], // wd3
    };
    float* out = (float*)d_out;

    float *t1,*x1,*xd1,*t2,*x2,*xd2,*t3,*x3,*x4,*m2,*m3;
    int *l1,*l2,*l3,*cnt;
    float *wr[10];
    cudaGetSymbolAddress((void**)&t1 , g_t1 );
    cudaGetSymbolAddress((void**)&x1 , g_x1 );
    cudaGetSymbolAddress((void**)&xd1, g_xd1);
    cudaGetSymbolAddress((void**)&t2 , g_t2 );
    cudaGetSymbolAddress((void**)&x2 , g_x2 );
    cudaGetSymbolAddress((void**)&xd2, g_xd2);
    cudaGetSymbolAddress((void**)&t3 , g_t3 );
    cudaGetSymbolAddress((void**)&x3 , g_x3 );
    cudaGetSymbolAddress((void**)&x4 , g_x4 );
    cudaGetSymbolAddress((void**)&m2 , g_m2 );
    cudaGetSymbolAddress((void**)&m3 , g_m3 );
    cudaGetSymbolAddress((void**)&l1 , g_list1);
    cudaGetSymbolAddress((void**)&l2 , g_list2);
    cudaGetSymbolAddress((void**)&l3 , g_list3);
    cudaGetSymbolAddress((void**)&cnt, g_cnt);
    cudaGetSymbolAddress((void**)&wr[0], g_w1a);
    cudaGetSymbolAddress((void**)&wr[1], g_w1d);
    cudaGetSymbolAddress((void**)&wr[2], g_w1b);
    cudaGetSymbolAddress((void**)&wr[3], g_wd1);
    cudaGetSymbolAddress((void**)&wr[4], g_w2a);
    cudaGetSymbolAddress((void**)&wr[5], g_w2b);
    cudaGetSymbolAddress((void**)&wr[6], g_wd2);
    cudaGetSymbolAddress((void**)&wr[7], g_w3a);
    cudaGetSymbolAddress((void**)&wr[8], g_w3b);
    cudaGetSymbolAddress((void**)&wr[9], g_wd3);

    // repack args
    RepackArgs ra;
    const int cins[10]  = {3, 3, 64, 64, 128, 128, 128, 256, 256, 256};
    const int couts[10] = {64,64, 64,128, 128, 128, 256, 256, 256, 128};
    const int k3s[10]   = {27, 1, 27, 27,  27,  27,  27,  27,  27,  27};
    int off = 0;
    for (int i = 0; i < 10; i++){
        ra.src[i] = w[i]; ra.dst[i] = wr[i];
        ra.cin[i] = cins[i]; ra.cout[i] = couts[i]; ra.k3[i] = k3s[i];
        ra.start[i] = off;
        off += cins[i]*couts[i]*k3s[i];
    }
    ra.ntot = off;

    // [0] repacks + cnt reset
    repack_all_k<<<(ra.ntot + 255)/256, 256>>>(ra);
    // [1] m2
    down_mask_k<<<(NB*32768 + 255)/256, 256>>>(mask, m2, 64, 32);
    // [2] l1, l2, m3
    fuse_k<<<(NB*262144 + NB*32768 + NB*4096 + 255)/256, 256>>>(mask, m2, m3, l1, l2, cnt);
    // [3] l3
    build_list_k<<<(NB*4096 + 255)/256, 256>>>(m3, NB*4096, l3, cnt+2);

    // [4] stage1a (CIN=3, NCDHW in)
    conv_s_k<3,64,3,64><<<8192,64>>>(x, wr[0], mask, l1, cnt+0, 64, 64, t1);
    // [5] stage1b  <-- ncu-captured launch
    convp_k<64,64,16,64><<<8192,64>>>(t1, wr[2], mask, l1, cnt+0, 64,64,1,
                                      nullptr, x, wr[1], x1);
    // down1: outputs only at m2-active sites
    convp_k<64,128,16,64><<<1024,128>>>(x1, wr[3], mask, l2, cnt+1, 64,32,2,
                                        nullptr, nullptr, nullptr, xd1);
    // stage 2
    convp_k<128,128,16,64><<<1024,128>>>(xd1, wr[4], m2, l2, cnt+1, 32,32,1,
                                         nullptr, nullptr, nullptr, t2);
    fill_k<<<4096,256>>>(xd1, m2, x2, 128, NB*32768*128);
    convp_k<128,128,16,64><<<1024,128>>>(t2, wr[5], m2, l2, cnt+1, 32,32,1,
                                         xd1, nullptr, nullptr, x2);
    // down2 (dense)
    convp_k<128,256,16,32><<<256,256>>>(x2, wr[6], nullptr, nullptr, nullptr,
                                        32,16,2, nullptr, nullptr, nullptr, xd2);
    // stage 3
    convp_k<256,256,16,32><<<256,256>>>(xd2, wr[7], nullptr, l3, cnt+2, 16,16,1,
                                        nullptr, nullptr, nullptr, t3);
    fill_k<<<2048,256>>>(xd2, nullptr, x3, 256, NB*4096*256);
    convp_k<256,256,16,32><<<256,256>>>(t3, wr[8], m3, l3, cnt+2, 16,16,1,
                                        xd2, nullptr, nullptr, x3);
    // down3 (dense)
    convp_k<256,128,16,8><<<128,128>>>(x3, wr[9], nullptr, nullptr, nullptr,
                                       16,8,2, nullptr, nullptr, nullptr, x4);
    // pooled head
    reduce_k<<<2,128>>>(x4, out);
}

// round 6
// speedup vs baseline: 2.9389x; 1.2154x over previous
#include <cuda_runtime.h>

#define NB 2
#define NEG 0.2f

// ---------------- scratch (__device__ globals; no allocation) ----------------
// All intermediates are CHANNEL-LAST: [b][spatial][C]
__device__ float g_t1 [NB*64*64*64*64];
__device__ float g_x1 [NB*64*64*64*64];
__device__ float g_xd1[NB*32*32*32*128];
__device__ float g_t2 [NB*32*32*32*128];
__device__ float g_x2 [NB*32*32*32*128];
__device__ float g_xd2[NB*16*16*16*256];
__device__ float g_t3 [NB*16*16*16*256];
__device__ float g_x3 [NB*16*16*16*256];
__device__ float g_x4 [NB*8*8*8*128];
__device__ float g_m2 [NB*32*32*32];
__device__ float g_m3 [NB*16*16*16];
__device__ int   g_list1[NB*64*64*64];
__device__ int   g_list2[NB*32*32*32];
__device__ int   g_list3[NB*16*16*16];
__device__ int   g_cnt[3];
// repacked weights: [tap][cin][cout], cout contiguous
__device__ float g_w1a[27*3*64];
__device__ float g_w1b[27*64*64];
__device__ float g_w1d[3*64];
__device__ float g_wd1[27*64*128];
__device__ float g_w2a[27*128*128];
__device__ float g_w2b[27*128*128];
__device__ float g_wd2[27*128*256];
__device__ float g_w3a[27*256*256];
__device__ float g_w3b[27*256*256];
__device__ float g_wd3[27*256*128];

__device__ __forceinline__ float lrelu(float v){ return v >= 0.f ? v : NEG*v; }
__device__ __forceinline__ unsigned sm_addr(const void* p){
    return (unsigned)__cvta_generic_to_shared(p);
}

// ---------------- setup kernels ----------------
struct RepackArgs {
    const float* src[10];
    float*       dst[10];
    int cin[10], cout[10], k3[10], start[10];
    int ntot;
};

__global__ void repack_all_k(RepackArgs a){
    int idx = blockIdx.x*blockDim.x + threadIdx.x;
    if (idx < 3) g_cnt[idx] = 0;
    if (idx >= a.ntot) return;
    int s = 0;
    #pragma unroll
    for (int k = 1; k < 10; k++) if (idx >= a.start[k]) s = k;
    int i = idx - a.start[s];
    int CIN = a.cin[s], COUT = a.cout[s], K3 = a.k3[s];
    int oc = i / (CIN*K3);
    int r  = i % (CIN*K3);
    int ic = r / K3;
    int k  = r % K3;
    a.dst[s][(k*CIN + ic)*COUT + oc] = a.src[s][i];
}

__global__ void down_mask_k(const float* __restrict__ in, float* __restrict__ out,
                            int Din, int Dout){
    int i = blockIdx.x*blockDim.x + threadIdx.x;
    int tot = NB*Dout*Dout*Dout;
    if (i >= tot) return;
    int ox = i % Dout, t = i / Dout;
    int oy = t % Dout; t /= Dout;
    int oz = t % Dout; int b = t / Dout;
    float m = 0.f;
    for (int kz = 0; kz < 3; kz++){
        int iz = 2*oz - 1 + kz; if ((unsigned)iz >= (unsigned)Din) continue;
        for (int ky = 0; ky < 3; ky++){
            int iy = 2*oy - 1 + ky; if ((unsigned)iy >= (unsigned)Din) continue;
            for (int kx = 0; kx < 3; kx++){
                int ix = 2*ox - 1 + kx; if ((unsigned)ix >= (unsigned)Din) continue;
                m = fmaxf(m, in[((b*Din + iz)*Din + iy)*Din + ix]);
            }
        }
    }
    out[i] = m;
}

__global__ void fuse_k(const float* __restrict__ mask, const float* __restrict__ m2,
                       float* __restrict__ m3, int* __restrict__ l1,
                       int* __restrict__ l2, int* __restrict__ cnt){
    const int A = NB*262144, B = NB*32768, C = NB*4096;
    int idx = blockIdx.x*blockDim.x + threadIdx.x;
    if (idx < A){
        if (mask[idx] != 0.f){ int p = atomicAdd(cnt+0, 1); l1[p] = idx; }
    } else if (idx < A+B){
        int i = idx - A;
        if (m2[i] != 0.f){ int p = atomicAdd(cnt+1, 1); l2[p] = i; }
    } else if (idx < A+B+C){
        int i = idx - A - B;
        int ox = i % 16, t = i / 16;
        int oy = t % 16; t /= 16;
        int oz = t % 16; int b = t / 16;
        float m = 0.f;
        for (int kz = 0; kz < 3; kz++){
            int iz = 2*oz - 1 + kz; if ((unsigned)iz >= 32u) continue;
            for (int ky = 0; ky < 3; ky++){
                int iy = 2*oy - 1 + ky; if ((unsigned)iy >= 32u) continue;
                for (int kx = 0; kx < 3; kx++){
                    int ix = 2*ox - 1 + kx; if ((unsigned)ix >= 32u) continue;
                    m = fmaxf(m, m2[((b*32 + iz)*32 + iy)*32 + ix]);
                }
            }
        }
        m3[i] = m;
    }
}

__global__ void build_list_k(const float* __restrict__ m, int tot,
                             int* __restrict__ list, int* __restrict__ cnt){
    int i = blockIdx.x*blockDim.x + threadIdx.x;
    if (i < tot && m[i] != 0.f){
        int p = atomicAdd(cnt, 1);
        list[p] = i;
    }
}

__global__ void fill_k(const float* __restrict__ in, const float* __restrict__ m,
                       float* __restrict__ out, int C, int n){
    int i  = blockIdx.x*blockDim.x + threadIdx.x;
    int st = gridDim.x*blockDim.x;
    for (int j = i; j < n; j += st){
        float v = in[j];
        float r = lrelu(v);
        if (m && m[j/C] == 0.f) r = 0.f;
        out[j] = r;
    }
}

// ---------------- simple conv (stage-1a: CIN=3, NCDHW in, VB=8, grid-stride) --
template<int CIN, int COUT, int CINC, int VB>
__global__ void __launch_bounds__(COUT) conv_s_k(
    const float* __restrict__ in, const float* __restrict__ wr,
    const float* __restrict__ in_mask,
    const int* __restrict__ list, const int* __restrict__ cnt,
    int Din, int Dout,
    float* __restrict__ out)
{
    __shared__ int s_base[VB];
    __shared__ int s_out [VB];
    __shared__ float s_in[VB][CINC];

    const int tid   = threadIdx.x;
    const int Din3  = Din*Din*Din;
    const int Dout3 = Dout*Dout*Dout;
    const int n     = *cnt;

    for (int vbase = blockIdx.x*VB; vbase < n; vbase += gridDim.x*VB){
        int vb=0,vz=0,vy=0,vx=0,vvalid=0;
        if (tid < VB){
            int vi = vbase + tid;
            int ob = -1;
            if (vi < n){
                int id = list[vi];
                vx = id % Dout; id /= Dout;
                vy = id % Dout; id /= Dout;
                vz = id % Dout; vb = id / Dout;
                ob = vb*Dout3 + (vz*Dout + vy)*Dout + vx;
                vvalid = 1;
            }
            s_out[tid] = ob;
        }
        __syncthreads();

        float acc[VB];
        #pragma unroll
        for (int v = 0; v < VB; v++) acc[v] = 0.f;

        for (int t = 0; t < 27; t++){
            int pred = 0;
            if (tid < VB){
                int base = -1;
                if (vvalid){
                    int kz = t/9, ky = (t/3)%3, kx = t%3;
                    int iz = vz - 1 + kz, iy = vy - 1 + ky, ix = vx - 1 + kx;
                    if ((unsigned)iz < (unsigned)Din && (unsigned)iy < (unsigned)Din &&
                        (unsigned)ix < (unsigned)Din){
                        int sp = (iz*Din + iy)*Din + ix;
                        if (in_mask[vb*Din3 + sp] != 0.f)
                            base = vb*CIN*Din3 + sp;   // NCDHW
                    }
                }
                s_base[tid] = base;
                pred = (base >= 0);
            }
            if (!__syncthreads_or(pred)) continue;

            float wreg[CINC];
            #pragma unroll
            for (int c = 0; c < CINC; c++)
                wreg[c] = wr[(t*CIN + c)*COUT + tid];
            #pragma unroll 1
            for (int i = tid; i < CINC*VB; i += COUT){
                int v = i / CINC, c = i % CINC;
                int base = s_base[v];
                s_in[v][c] = (base >= 0) ? in[base + c*Din3] : 0.f;
            }
            __syncthreads();
            #pragma unroll
            for (int v = 0; v < VB; v++){
                float a = acc[v];
                #pragma unroll
                for (int c = 0; c < CINC; c++)
                    a = fmaf(wreg[c], s_in[v][c], a);
                acc[v] = a;
            }
            __syncthreads();
        }

        #pragma unroll
        for (int v = 0; v < VB; v++){
            int ob = s_out[v];
            if (ob < 0) continue;
            out[ob*COUT + tid] = lrelu(acc[v]);
        }
        __syncthreads();
    }
}

// ---------------- pipelined conv (channel-last, cp.async, grid-stride) -------
template<int CIN, int COUT, int CINC, int VB>
__global__ void __launch_bounds__(COUT) convp_k(
    const float* __restrict__ in, const float* __restrict__ wr,
    const float* __restrict__ in_mask,
    const int* __restrict__ list, const int* __restrict__ cnt,
    int Din, int Dout, int stride,
    const float* __restrict__ ident,
    const float* __restrict__ identx, const float* __restrict__ identw,
    float* __restrict__ out)
{
    constexpr int CHUNKS = CIN/CINC;
    constexpr int F4 = VB*CINC/4;
    constexpr int PT = (F4 + COUT - 1)/COUT;
    __shared__ int s_tap[27];
    __shared__ int s_ntap;
    __shared__ int s_base[27][VB];
    __shared__ int s_out[VB];
    __shared__ __align__(16) float4 s_in[2][F4];

    const int tid   = threadIdx.x;
    const int Din3  = Din*Din*Din;
    const int Dout3 = Dout*Dout*Dout;
    const int n     = list ? *cnt : NB*Dout3;

    for (int vbase = blockIdx.x*VB; vbase < n; vbase += gridDim.x*VB){
        int vb=0,vz=0,vy=0,vx=0,vvalid=0;
        if (tid < VB){
            int vi = vbase + tid;
            int ob = -1;
            if (vi < n){
                int id = list ? list[vi] : vi;
                vx = id % Dout; id /= Dout;
                vy = id % Dout; id /= Dout;
                vz = id % Dout; vb = id / Dout;
                ob = vb*Dout3 + (vz*Dout + vy)*Dout + vx;
                vvalid = 1;
            }
            s_out[tid] = ob;
        }
        if (tid == 0) s_ntap = 0;
        __syncthreads();

        for (int t = 0; t < 27; t++){
            int pred = 0;
            if (tid < VB){
                int base = -1;
                if (vvalid){
                    int kz = t/9, ky = (t/3)%3, kx = t%3;
                    int iz = vz*stride - 1 + kz;
                    int iy = vy*stride - 1 + ky;
                    int ix = vx*stride - 1 + kx;
                    if ((unsigned)iz < (unsigned)Din && (unsigned)iy < (unsigned)Din &&
                        (unsigned)ix < (unsigned)Din){
                        int sp = (iz*Din + iy)*Din + ix;
                        if (!in_mask || in_mask[vb*Din3 + sp] != 0.f)
                            base = (vb*Din3 + sp)*CIN;
                    }
                }
                s_base[t][tid] = base;
                pred = (base >= 0);
            }
            int any = __syncthreads_or(pred);
            if (any && tid == 0) s_tap[s_ntap++] = t;
        }
        __syncthreads();
        const int ntap = s_ntap;
        const int nit  = ntap * CHUNKS;

        float acc[VB];
        #pragma unroll
        for (int v = 0; v < VB; v++) acc[v] = 0.f;

        auto issue = [&](int it, int buf){
            int tap = s_tap[it/CHUNKS];
            int cc  = (it%CHUNKS)*CINC;
            #pragma unroll
            for (int k = 0; k < PT; k++){
                int j = tid + k*COUT;
                if ((F4 % COUT == 0) || (j < F4)){
                    int v = j/(CINC/4), c4 = j%(CINC/4);
                    int base = s_base[tap][v];
                    const float* src = (base >= 0) ? (in + base + cc + c4*4) : in;
                    int sz = (base >= 0) ? 16 : 0;
                    unsigned dst = sm_addr(&s_in[buf][j]);
                    asm volatile("cp.async.ca.shared.global [%0], [%1], 16, %2;\n"
                                 :: "r"(dst), "l"(src), "r"(sz));
                }
            }
            asm volatile("cp.async.commit_group;\n");
        };

        if (nit > 0) issue(0, 0);
        for (int it = 0; it < nit; it++){
            int buf = it & 1;
            int tap = s_tap[it/CHUNKS];
            int cc  = (it%CHUNKS)*CINC;
            float wreg[CINC];
            #pragma unroll
            for (int c = 0; c < CINC; c++)
                wreg[c] = wr[(tap*CIN + cc + c)*COUT + tid];
            if (it + 1 < nit){
                issue(it + 1, buf ^ 1);
                asm volatile("cp.async.wait_group 1;\n");
            } else {
                asm volatile("cp.async.wait_group 0;\n");
            }
            __syncthreads();
            const float4* rows = s_in[buf];
            #pragma unroll
            for (int v = 0; v < VB; v++){
                float a = acc[v];
                #pragma unroll
                for (int q = 0; q < CINC/4; q++){
                    float4 r = rows[v*(CINC/4) + q];
                    a = fmaf(wreg[4*q+0], r.x, a);
                    a = fmaf(wreg[4*q+1], r.y, a);
                    a = fmaf(wreg[4*q+2], r.z, a);
                    a = fmaf(wreg[4*q+3], r.w, a);
                }
                acc[v] = a;
            }
            __syncthreads();
        }

        #pragma unroll
        for (int v = 0; v < VB; v++){
            int ob = s_out[v];
            if (ob < 0) continue;
            float val = acc[v];
            if (ident) val += ident[ob*COUT + tid];
            if (identw){
                int b = ob / Dout3, sp = ob - b*Dout3;
                const float* xp = identx + b*3*Dout3 + sp;
                val = fmaf(identw[tid],          xp[0],       val);
                val = fmaf(identw[COUT + tid],   xp[Dout3],   val);
                val = fmaf(identw[2*COUT + tid], xp[2*Dout3], val);
            }
            out[ob*COUT + tid] = lrelu(val);
        }
        __syncthreads();
    }
}

// ---------------- final pooled reduce (channel-last x4) ----------------
__global__ void reduce_k(const float* __restrict__ x4, float* __restrict__ out){
    int b  = blockIdx.x;
    int oc = threadIdx.x;
    const float* p = x4 + b*512*128 + oc;
    float s = 0.f, mx = -3.402823466e38f;
    #pragma unroll 8
    for (int sp = 0; sp < 512; sp++){
        float v = p[sp*128];
        s += v; mx = fmaxf(mx, v);
    }
    out[b*256 + oc]       = s * (1.f/512.f);
    out[b*256 + 128 + oc] = mx;
}

// ---------------- launch ----------------
extern "C" void kernel_launch(void* const* d_in, const int* in_sizes, int n_in,
                              void* d_out, int out_size){
    const float* x    = (const float*)d_in[0];
    const float* mask = (const float*)d_in[1];
    const float* w[10] = {
        (const float*)d_in[2],  // w1a
        (const float*)d_in[4],  // w1d (K3=1)
        (const float*)d_in[3],  // w1b
        (const float*)d_in[5],  // wd1
        (const float*)d_in[6],  // w2a
        (const float*)d_in[7],  // w2b
        (const float*)d_in[8],  // wd2
        (const float*)d_in[9],  // w3a
        (const float*)d_in[10], // w3b
        (const float*)d_in[11], // wd3
    };
    float* out = (float*)d_out;

    float *t1,*x1,*xd1,*t2,*x2,*xd2,*t3,*x3,*x4,*m2,*m3;
    int *l1,*l2,*l3,*cnt;
    float *wr[10];
    cudaGetSymbolAddress((void**)&t1 , g_t1 );
    cudaGetSymbolAddress((void**)&x1 , g_x1 );
    cudaGetSymbolAddress((void**)&xd1, g_xd1);
    cudaGetSymbolAddress((void**)&t2 , g_t2 );
    cudaGetSymbolAddress((void**)&x2 , g_x2 );
    cudaGetSymbolAddress((void**)&xd2, g_xd2);
    cudaGetSymbolAddress((void**)&t3 , g_t3 );
    cudaGetSymbolAddress((void**)&x3 , g_x3 );
    cudaGetSymbolAddress((void**)&x4 , g_x4 );
    cudaGetSymbolAddress((void**)&m2 , g_m2 );
    cudaGetSymbolAddress((void**)&m3 , g_m3 );
    cudaGetSymbolAddress((void**)&l1 , g_list1);
    cudaGetSymbolAddress((void**)&l2 , g_list2);
    cudaGetSymbolAddress((void**)&l3 , g_list3);
    cudaGetSymbolAddress((void**)&cnt, g_cnt);
    cudaGetSymbolAddress((void**)&wr[0], g_w1a);
    cudaGetSymbolAddress((void**)&wr[1], g_w1d);
    cudaGetSymbolAddress((void**)&wr[2], g_w1b);
    cudaGetSymbolAddress((void**)&wr[3], g_wd1);
    cudaGetSymbolAddress((void**)&wr[4], g_w2a);
    cudaGetSymbolAddress((void**)&wr[5], g_w2b);
    cudaGetSymbolAddress((void**)&wr[6], g_wd2);
    cudaGetSymbolAddress((void**)&wr[7], g_w3a);
    cudaGetSymbolAddress((void**)&wr[8], g_w3b);
    cudaGetSymbolAddress((void**)&wr[9], g_wd3);

    RepackArgs ra;
    const int cins[10]  = {3, 3, 64, 64, 128, 128, 128, 256, 256, 256};
    const int couts[10] = {64,64, 64,128, 128, 128, 256, 256, 256, 128};
    const int k3s[10]   = {27, 1, 27, 27,  27,  27,  27,  27,  27,  27};
    int off = 0;
    for (int i = 0; i < 10; i++){
        ra.src[i] = w[i]; ra.dst[i] = wr[i];
        ra.cin[i] = cins[i]; ra.cout[i] = couts[i]; ra.k3[i] = k3s[i];
        ra.start[i] = off;
        off += cins[i]*couts[i]*k3s[i];
    }
    ra.ntot = off;

    repack_all_k<<<(ra.ntot + 255)/256, 256>>>(ra);
    down_mask_k<<<(NB*32768 + 255)/256, 256>>>(mask, m2, 64, 32);
    fuse_k<<<(NB*262144 + NB*32768 + NB*4096 + 255)/256, 256>>>(mask, m2, m3, l1, l2, cnt);
    build_list_k<<<(NB*4096 + 255)/256, 256>>>(m3, NB*4096, l3, cnt+2);

    // stage1a: VB=8 (small tap-union waste at 5% sparsity)
    conv_s_k<3,64,3,8><<<2048,64>>>(x, wr[0], mask, l1, cnt+0, 64, 64, t1);
    // stage1b: VB=8 -> ~9.7 taps/block instead of 26 (58G -> ~1G MACs)
    convp_k<64,64,16,8><<<4096,64>>>(t1, wr[2], mask, l1, cnt+0, 64,64,1,
                                     nullptr, x, wr[1], x1);
    // down1: VB=8 (input mask 5%)
    convp_k<64,128,16,8><<<2048,128>>>(x1, wr[3], mask, l2, cnt+1, 64,32,2,
                                       nullptr, nullptr, nullptr, xd1);
    // stage 2 (m2 ~75% -> dense-ish; keep VB=64)
    convp_k<128,128,16,64><<<1024,128>>>(xd1, wr[4], m2, l2, cnt+1, 32,32,1,
                                         nullptr, nullptr, nullptr, t2);
    fill_k<<<4096,256>>>(xd1, m2, x2, 128, NB*32768*128);
    convp_k<128,128,16,64><<<1024,128>>>(t2, wr[5], m2, l2, cnt+1, 32,32,1,
                                         xd1, nullptr, nullptr, x2);
    // down2 (dense)
    convp_k<128,256,16,32><<<256,256>>>(x2, wr[6], nullptr, nullptr, nullptr,
                                        32,16,2, nullptr, nullptr, nullptr, xd2);
    // stage 3 (dense)
    convp_k<256,256,16,32><<<256,256>>>(xd2, wr[7], nullptr, l3, cnt+2, 16,16,1,
                                        nullptr, nullptr, nullptr, t3);
    fill_k<<<2048,256>>>(xd2, nullptr, x3, 256, NB*4096*256);
    convp_k<256,256,16,32><<<256,256>>>(t3, wr[8], m3, l3, cnt+2, 16,16,1,
                                        xd2, nullptr, nullptr, x3);
    // down3 (dense)
    convp_k<256,128,16,8><<<128,128>>>(x3, wr[9], nullptr, nullptr, nullptr,
                                       16,8,2, nullptr, nullptr, nullptr, x4);
    reduce_k<<<2,128>>>(x4, out);
}